// round 11
// baseline (speedup 1.0000x reference)
#include <cuda_runtime.h>
#include <cuda_bf16.h>
#include <cstdint>

// Problem constants
#define B_   1024
#define N_   32
#define D_   512
#define H_   4
#define HD_  128
#define QKV_COLS 1536
#define M_ROWS   32768
#define KT   1536              // tripled K (3 * 512)

// GEMM tiling (warp-level mma.sync path — compiles for compute_103)
#define BM 128
#define BN 128
#define BK 64                       // bf16 per K-chunk (128B data per row)
#define STAGES 3
#define ROWB 144                    // smem row stride bytes (128 data + 16 pad)
#define A_ST (BM * ROWB)            // 18432
#define ST_BYTES (2 * A_ST)         // 36864 (A tile + B tile)
#define GEMM_SMEM (STAGES * ST_BYTES)  // 110592
#define NK (KT / BK)                // 24

// Scratch (device globals — allocation-free per harness rules)
__device__ float         g_qkv [(size_t)M_ROWS * QKV_COLS];  // fp32 (B*N,1536)
__device__ __nv_bfloat16 g_xa  [(size_t)M_ROWS * KT];        // x  split [Ah|Al|Ah]
__device__ __nv_bfloat16 g_ctxa[(size_t)M_ROWS * KT];        // ctx split [Ah|Al|Ah]
__device__ __nv_bfloat16 g_wina[(size_t)QKV_COLS * KT];      // W_in  split [Bh|Bh|Bl]
__device__ __nv_bfloat16 g_wouta[(size_t)D_ * KT];           // W_out split [Bh|Bh|Bl]

// ---------------------------------------------------------------------------
// PTX helpers (all arch-agnostic: cp.async / ldmatrix / mma.sync)
// ---------------------------------------------------------------------------
__device__ __forceinline__ uint32_t smem_u32(const void* p) {
    uint32_t a;
    asm("{ .reg .u64 t; cvta.to.shared.u64 t, %1; cvt.u32.u64 %0, t; }"
        : "=r"(a) : "l"(p));
    return a;
}

__device__ __forceinline__ void cp_async16(uint32_t s, const void* g) {
    asm volatile("cp.async.cg.shared.global [%0], [%1], 16;"
                 :: "r"(s), "l"(g) : "memory");
}
#define CP_COMMIT() asm volatile("cp.async.commit_group;" ::: "memory")
#define CP_WAIT(n)  asm volatile("cp.async.wait_group %0;" :: "n"(n) : "memory")

__device__ __forceinline__ void ldsm4(uint32_t* r, uint32_t addr) {
    asm volatile("ldmatrix.sync.aligned.m8n8.x4.shared.b16 {%0,%1,%2,%3}, [%4];"
                 : "=r"(r[0]), "=r"(r[1]), "=r"(r[2]), "=r"(r[3]) : "r"(addr));
}

__device__ __forceinline__ void mma16816(float* d, const uint32_t* a,
                                         const uint32_t* b) {
    asm volatile("mma.sync.aligned.m16n8k16.row.col.f32.bf16.bf16.f32 "
                 "{%0,%1,%2,%3}, {%4,%5,%6,%7}, {%8,%9}, {%0,%1,%2,%3};"
                 : "+f"(d[0]), "+f"(d[1]), "+f"(d[2]), "+f"(d[3])
                 : "r"(a[0]), "r"(a[1]), "r"(a[2]), "r"(a[3]),
                   "r"(b[0]), "r"(b[1]));
}

// ---------------------------------------------------------------------------
// Split-precision conversion kernels (fp32 -> tripled bf16, K=512 -> 1536)
// ---------------------------------------------------------------------------
__device__ __forceinline__ void split_bf16(float v, __nv_bfloat16& hi, __nv_bfloat16& lo) {
    hi = __float2bfloat16_rn(v);
    lo = __float2bfloat16_rn(v - __bfloat162float(hi));
}

// A-side layout: [Ah | Al | Ah]
__global__ void conv_a(const float* __restrict__ src, __nv_bfloat16* __restrict__ dst,
                       int total4) {
    int idx = blockIdx.x * 256 + threadIdx.x;
    if (idx >= total4) return;
    int row = idx >> 7;            // 128 float4 per 512-col row
    int c4  = (idx & 127) << 2;
    float4 v = *(const float4*)(src + (size_t)row * 512 + c4);
    __nv_bfloat16 h0, h1, h2, h3, l0, l1, l2, l3;
    split_bf16(v.x, h0, l0); split_bf16(v.y, h1, l1);
    split_bf16(v.z, h2, l2); split_bf16(v.w, h3, l3);
    __nv_bfloat16* d = dst + (size_t)row * KT + c4;
    ((__nv_bfloat162*)(d       ))[0] = __nv_bfloat162(h0, h1);
    ((__nv_bfloat162*)(d       ))[1] = __nv_bfloat162(h2, h3);
    ((__nv_bfloat162*)(d +  512))[0] = __nv_bfloat162(l0, l1);
    ((__nv_bfloat162*)(d +  512))[1] = __nv_bfloat162(l2, l3);
    ((__nv_bfloat162*)(d + 1024))[0] = __nv_bfloat162(h0, h1);
    ((__nv_bfloat162*)(d + 1024))[1] = __nv_bfloat162(h2, h3);
}

// B-side layout: [Bh | Bh | Bl]
__global__ void conv_b(const float* __restrict__ src, __nv_bfloat16* __restrict__ dst,
                       int total4) {
    int idx = blockIdx.x * 256 + threadIdx.x;
    if (idx >= total4) return;
    int row = idx >> 7;
    int c4  = (idx & 127) << 2;
    float4 v = *(const float4*)(src + (size_t)row * 512 + c4);
    __nv_bfloat16 h0, h1, h2, h3, l0, l1, l2, l3;
    split_bf16(v.x, h0, l0); split_bf16(v.y, h1, l1);
    split_bf16(v.z, h2, l2); split_bf16(v.w, h3, l3);
    __nv_bfloat16* d = dst + (size_t)row * KT + c4;
    ((__nv_bfloat162*)(d       ))[0] = __nv_bfloat162(h0, h1);
    ((__nv_bfloat162*)(d       ))[1] = __nv_bfloat162(h2, h3);
    ((__nv_bfloat162*)(d +  512))[0] = __nv_bfloat162(h0, h1);
    ((__nv_bfloat162*)(d +  512))[1] = __nv_bfloat162(h2, h3);
    ((__nv_bfloat162*)(d + 1024))[0] = __nv_bfloat162(l0, l1);
    ((__nv_bfloat162*)(d + 1024))[1] = __nv_bfloat162(l2, l3);
}

// ---------------------------------------------------------------------------
// HMMA GEMM: C[M, Nout](fp32) = A[M, KT](bf16) @ B[Nout, KT](bf16)^T + bias
// CTA 128x128, 4 warps (2x2), warp tile 64x64, K-chunk 64, 3-stage cp.async.
// smem rows stride 144B: ldsm 8-row phase covers all 32 banks (4-bank
// step/row); cp.async 16B phases are one row each -> conflict-free.
// One barrier per K-chunk; single-buffered fragments (proven body shape).
// ---------------------------------------------------------------------------
__global__ __launch_bounds__(128, 2)
void gemm_mma(const __nv_bfloat16* __restrict__ A,
              const __nv_bfloat16* __restrict__ Bm,
              const float* __restrict__ bias, float* __restrict__ C, int Nout)
{
    extern __shared__ __align__(128) char smem[];
    const int tid  = threadIdx.x;
    const int wid  = tid >> 5;
    const int lane = tid & 31;
    const int m0 = blockIdx.y * BM;
    const int n0 = blockIdx.x * BN;
    const int warp_m = (wid >> 1) * 64;   // 0 or 64
    const int warp_n = (wid & 1) * 64;    // 0 or 64
    const uint32_t sbase = smem_u32(smem);

    // load thread mapping: 1024 16B-chunks per tile, 8 per thread per tile
    const int lr = tid >> 3;        // 0..15 base row
    const int lc = tid & 7;         // 16B chunk in row (8 per 128B row)

    float acc[4][8][4];
#pragma unroll
    for (int mi = 0; mi < 4; mi++)
#pragma unroll
        for (int ni = 0; ni < 8; ni++)
#pragma unroll
            for (int r = 0; r < 4; r++) acc[mi][ni][r] = 0.f;

    auto load_stage = [&](int kc, int b) {
        const uint32_t as = sbase + b * ST_BYTES;
        const uint32_t bs = as + A_ST;
        const __nv_bfloat16* Ag = A  + (size_t)m0 * KT + kc * BK;
        const __nv_bfloat16* Bg = Bm + (size_t)n0 * KT + kc * BK;
#pragma unroll
        for (int i = 0; i < 8; i++) {
            int r = lr + i * 16;
            cp_async16(as + r * ROWB + lc * 16, Ag + (size_t)r * KT + lc * 8);
        }
#pragma unroll
        for (int i = 0; i < 8; i++) {
            int r = lr + i * 16;
            cp_async16(bs + r * ROWB + lc * 16, Bg + (size_t)r * KT + lc * 8);
        }
        CP_COMMIT();
    };

    load_stage(0, 0);
    load_stage(1, 1);

    // fragment addresses (constant per thread, add stage/k offsets)
    const uint32_t a_addr0 = sbase + (warp_m + (lane & 15)) * ROWB + (lane >> 4) * 16;
    const uint32_t b_addr0 = sbase + A_ST
                           + (warp_n + ((lane >> 4) << 3) + (lane & 7)) * ROWB
                           + (((lane >> 3) & 1) << 4);

    int buf = 0;    // buffer being consumed this iteration
    int lbuf = 2;   // buffer to load into at end of iteration ((buf+2)%3)

    for (int k = 0; k < NK; k++) {
        if (k < NK - 1) { CP_WAIT(1); }
        else            { CP_WAIT(0); }
        __syncthreads();

        const uint32_t soff = buf * ST_BYTES;
#pragma unroll
        for (int ks = 0; ks < 4; ks++) {            // four k16 steps per chunk
            uint32_t af[4][4], bf[4][4];
#pragma unroll
            for (int mi = 0; mi < 4; mi++)
                ldsm4(af[mi], a_addr0 + soff + mi * 16 * ROWB + ks * 32);
#pragma unroll
            for (int nj = 0; nj < 4; nj++)
                ldsm4(bf[nj], b_addr0 + soff + nj * 16 * ROWB + ks * 32);
#pragma unroll
            for (int mi = 0; mi < 4; mi++) {
#pragma unroll
                for (int ni = 0; ni < 8; ni++) {
                    const uint32_t* bp = &bf[ni >> 1][(ni & 1) * 2];
                    mma16816(acc[mi][ni], af[mi], bp);
                }
            }
        }
        // no trailing barrier: iter-k writes target buf (k+2)%3 = (k-1)%3,
        // whose readers (iter k-1 ldsm) all passed this iter's top barrier.
        const int kn = k + 2;
        if (kn < NK) load_stage(kn, lbuf);
        buf  = (buf  == 2) ? 0 : buf  + 1;
        lbuf = (lbuf == 2) ? 0 : lbuf + 1;
    }

    // epilogue: bias + fp32 store (float2 per reg-pair)
#pragma unroll
    for (int mi = 0; mi < 4; mi++) {
#pragma unroll
        for (int ni = 0; ni < 8; ni++) {
            int row = m0 + warp_m + mi * 16 + (lane >> 2);
            int col = n0 + warp_n + ni * 8 + (lane & 3) * 2;
            float b0 = bias[col], b1 = bias[col + 1];
            float2 v0 = make_float2(acc[mi][ni][0] + b0, acc[mi][ni][1] + b1);
            float2 v1 = make_float2(acc[mi][ni][2] + b0, acc[mi][ni][3] + b1);
            *(float2*)(C + (size_t)row * Nout + col)       = v0;
            *(float2*)(C + (size_t)(row + 8) * Nout + col) = v1;
        }
    }
}

// ---------------------------------------------------------------------------
// Attention: one block per (b, h). 32 q x 32 k x 128 d. Output written
// directly in tripled-bf16 A-side layout [Ah | Al | Ah] into g_ctxa.
// ---------------------------------------------------------------------------
__global__ __launch_bounds__(128)
void attn_kernel(const float* __restrict__ qkv,
                 const unsigned char* __restrict__ pad,
                 __nv_bfloat16* __restrict__ ctxa)
{
    __shared__ float qs[32 * 129];
    __shared__ float ks[32 * 129];
    __shared__ float vs[32 * 129];
    __shared__ float sc[32 * 33];
    __shared__ int   spad[32];

    const int b = blockIdx.x >> 2;
    const int h = blockIdx.x & 3;
    const int tid = threadIdx.x;

    const float* base = qkv + (size_t)b * N_ * QKV_COLS + h * HD_;

    for (int idx = tid; idx < N_ * HD_; idx += 128) {
        int r = idx >> 7, c = idx & 127;
        qs[r * 129 + c] = base[(size_t)r * QKV_COLS            + c];
        ks[r * 129 + c] = base[(size_t)r * QKV_COLS + D_     + c];
        vs[r * 129 + c] = base[(size_t)r * QKV_COLS + 2 * D_ + c];
    }
    if (tid < 32) spad[tid] = pad[b * N_ + tid];
    __syncthreads();

    const int q = tid >> 2;
    const int kbase = (tid & 3) * 8;
    const float* qrow = &qs[q * 129];

    float acc[8];
#pragma unroll
    for (int i = 0; i < 8; i++) acc[i] = 0.f;

    for (int c0 = 0; c0 < HD_; c0 += 16) {
        float qreg[16];
#pragma unroll
        for (int c = 0; c < 16; c++) qreg[c] = qrow[c0 + c];
#pragma unroll
        for (int i = 0; i < 8; i++) {
            const float* krow = &ks[(kbase + i) * 129 + c0];
#pragma unroll
            for (int c = 0; c < 16; c++) acc[i] += qreg[c] * krow[c];
        }
    }

    const float scale = 0.08838834764831845f;  // 1/sqrt(128)
#pragma unroll
    for (int i = 0; i < 8; i++) {
        int k = kbase + i;
        float s = (k == q || spad[k]) ? -1e30f : acc[i] * scale;
        sc[q * 33 + k] = s;
    }
    __syncthreads();

    if (tid < 32) {
        float m = -1e30f;
#pragma unroll
        for (int k = 0; k < 32; k++) m = fmaxf(m, sc[tid * 33 + k]);
        float sum = 0.f;
#pragma unroll
        for (int k = 0; k < 32; k++) {
            float e = __expf(sc[tid * 33 + k] - m);
            sc[tid * 33 + k] = e;
            sum += e;
        }
        float inv = 1.f / sum;
#pragma unroll
        for (int k = 0; k < 32; k++) sc[tid * 33 + k] *= inv;
    }
    __syncthreads();

    {
        const int dq = tid & 3;
        float o[32];
#pragma unroll
        for (int j = 0; j < 32; j++) o[j] = 0.f;
        for (int k = 0; k < 32; k++) {
            float p = sc[q * 33 + k];
            const float* vrow = &vs[k * 129 + dq];
#pragma unroll
            for (int j = 0; j < 32; j++) o[j] += p * vrow[4 * j];
        }
        float* stg = &ks[q * 129 + dq];
#pragma unroll
        for (int j = 0; j < 32; j++) stg[4 * j] = o[j];
    }
    __syncthreads();

    // write tripled-bf16 ctx: [Ah | Al | Ah]
    __nv_bfloat16* outa = ctxa + (size_t)b * N_ * KT + h * HD_;
    for (int idx = tid; idx < N_ * HD_; idx += 128) {
        int r = idx >> 7, c = idx & 127;
        float v = ks[r * 129 + c];
        __nv_bfloat16 hi, lo;
        split_bf16(v, hi, lo);
        __nv_bfloat16* p = outa + (size_t)r * KT + c;
        p[0]    = hi;
        p[512]  = lo;
        p[1024] = hi;
    }
}

// ---------------------------------------------------------------------------
// Launch
// ---------------------------------------------------------------------------
extern "C" void kernel_launch(void* const* d_in, const int* in_sizes, int n_in,
                              void* d_out, int out_size)
{
    const float*         x     = (const float*)d_in[0];
    const unsigned char* pmask = (const unsigned char*)d_in[1];
    const float*         w_in  = (const float*)d_in[2];
    const float*         b_in  = (const float*)d_in[3];
    const float*         w_out = (const float*)d_in[4];
    const float*         b_out = (const float*)d_in[5];
    float*               out   = (float*)d_out;

    void *qkv_p, *xa_p, *ctxa_p, *wina_p, *wouta_p;
    cudaGetSymbolAddress(&qkv_p,   g_qkv);
    cudaGetSymbolAddress(&xa_p,    g_xa);
    cudaGetSymbolAddress(&ctxa_p,  g_ctxa);
    cudaGetSymbolAddress(&wina_p,  g_wina);
    cudaGetSymbolAddress(&wouta_p, g_wouta);
    float*         qkv   = (float*)qkv_p;
    __nv_bfloat16* xa    = (__nv_bfloat16*)xa_p;
    __nv_bfloat16* ctxa  = (__nv_bfloat16*)ctxa_p;
    __nv_bfloat16* wina  = (__nv_bfloat16*)wina_p;
    __nv_bfloat16* wouta = (__nv_bfloat16*)wouta_p;

    cudaFuncSetAttribute(gemm_mma, cudaFuncAttributeMaxDynamicSharedMemorySize,
                         GEMM_SMEM);

    // split-precision conversions
    {
        int t4 = M_ROWS * 128;
        conv_a<<<(t4 + 255) / 256, 256>>>(x, xa, t4);
    }
    {
        int t4 = QKV_COLS * 128;
        conv_b<<<(t4 + 255) / 256, 256>>>(w_in, wina, t4);
    }
    {
        int t4 = D_ * 128;
        conv_b<<<(t4 + 255) / 256, 256>>>(w_out, wouta, t4);
    }

    // 1) QKV projection: (32768 x 1536)
    {
        dim3 grid(QKV_COLS / BN, M_ROWS / BM);   // (12, 256)
        gemm_mma<<<grid, 128, GEMM_SMEM>>>(xa, wina, b_in, qkv, QKV_COLS);
    }

    // 2) attention (writes tripled-bf16 ctx)
    attn_kernel<<<B_ * H_, 128>>>(qkv, pmask, ctxa);

    // 3) output projection: (32768 x 512)
    {
        dim3 grid(D_ / BN, M_ROWS / BM);         // (4, 256)
        gemm_mma<<<grid, 128, GEMM_SMEM>>>(ctxa, wouta, b_out, out, D_);
    }
}